// round 5
// baseline (speedup 1.0000x reference)
#include <cuda_runtime.h>
#include <cuda_bf16.h>
#include <cstdint>

#define N_ROWS 16384
#define DDIM   2048
#define KCODES 1024

__device__ float g_enorm[KCODES];
__device__ int   g_best[N_ROWS];
__device__ float g_scores[(size_t)N_ROWS * KCODES];
__device__ __nv_bfloat16 g_xb[(size_t)N_ROWS * DDIM];
__device__ __nv_bfloat16 g_eb[(size_t)KCODES * DDIM];

// ---------------------------------------------------------------------------
#define ROWB   80                  // 64B payload + 16B pad (ldmatrix conflict-free)
#define STG    (384 * ROWB)        // stage: A 256 rows + B 128 rows = 30720 B
#define SMEM_P1 (4 * STG)          // 122880

static __device__ __forceinline__ uint32_t smem_u32(const void* p) {
    uint32_t a;
    asm("{ .reg .u64 t; cvta.to.shared.u64 t, %1; cvt.u32.u64 %0, t; }"
        : "=r"(a) : "l"(p));
    return a;
}

#define LDSM_X4(r, addr)                                                     \
    asm volatile("ldmatrix.sync.aligned.m8n8.x4.shared.b16 {%0,%1,%2,%3}, [%4];" \
        : "=r"((r)[0]), "=r"((r)[1]), "=r"((r)[2]), "=r"((r)[3]) : "r"(addr))

#define MMA_BF16(d, a, b0, b1)                                               \
    asm volatile("mma.sync.aligned.m16n8k16.row.col.f32.bf16.bf16.f32 "      \
        "{%0,%1,%2,%3}, {%4,%5,%6,%7}, {%8,%9}, {%0,%1,%2,%3};"              \
        : "+f"((d)[0]), "+f"((d)[1]), "+f"((d)[2]), "+f"((d)[3])             \
        : "r"((a)[0]), "r"((a)[1]), "r"((a)[2]), "r"((a)[3]),                \
          "r"(b0), "r"(b1))

#define CP16(dst, src)                                                       \
    asm volatile("cp.async.ca.shared.global [%0], [%1], 16;"                 \
                 :: "r"(dst), "l"(src))
#define CP_COMMIT() asm volatile("cp.async.commit_group;" ::: "memory")
#define CP_WAIT2()  asm volatile("cp.async.wait_group 2;" ::: "memory")

// ---------------------------------------------------------------------------
__global__ void convert_kernel(const float* __restrict__ src,
                               __nv_bfloat16* __restrict__ dst, int n4) {
    for (int i = blockIdx.x * blockDim.x + threadIdx.x; i < n4;
         i += gridDim.x * blockDim.x) {
        float4 v = reinterpret_cast<const float4*>(src)[i];
        __nv_bfloat162 a = __floats2bfloat162_rn(v.x, v.y);
        __nv_bfloat162 b = __floats2bfloat162_rn(v.z, v.w);
        uint2 u; memcpy(&u.x, &a, 4); memcpy(&u.y, &b, 4);
        reinterpret_cast<uint2*>(dst)[i] = u;
    }
}

// ---------------------------------------------------------------------------
__global__ void enorm_kernel(const float* __restrict__ e) {
    int k = blockIdx.x;
    const float4* row = reinterpret_cast<const float4*>(e + (size_t)k * DDIM);
    float s = 0.f;
    for (int i = threadIdx.x; i < DDIM / 4; i += blockDim.x) {
        float4 v = row[i];
        s += v.x * v.x + v.y * v.y + v.z * v.z + v.w * v.w;
    }
#pragma unroll
    for (int o = 16; o; o >>= 1) s += __shfl_xor_sync(0xffffffffu, s, o);
    __shared__ float ss[8];
    if ((threadIdx.x & 31) == 0) ss[threadIdx.x >> 5] = s;
    __syncthreads();
    if (threadIdx.x == 0) {
        float t = 0.f;
        for (int i = 0; i < (int)blockDim.x / 32; i++) t += ss[i];
        g_enorm[k] = 0.5f * t;
    }
}

// ---------------------------------------------------------------------------
// Pass 1: bf16 HMMA GEMM. CTA tile 256 rows x 128 codes, warp tile 64x64,
// KT=32 per stage, 4-stage cp.async pipeline. Stores raw dots.
// ---------------------------------------------------------------------------
__global__ __launch_bounds__(256, 1)
void pass1_gemm(void) {
    extern __shared__ char smem[];
    const uint32_t sbase = smem_u32(smem);

    const int tid  = threadIdx.x;
    const int lane = tid & 31;
    const int wid  = tid >> 5;
    const int wm   = wid & 3;            // 4 M-groups (64 rows each)
    const int wn   = wid >> 2;           // 2 N-groups (64 codes each)
    const int brow  = blockIdx.y * 256;
    const int bcode = blockIdx.x * 128;

    const __nv_bfloat16* xb = g_xb;
    const __nv_bfloat16* eb = g_eb;

    float acc[4][8][4];
#pragma unroll
    for (int mi = 0; mi < 4; mi++)
#pragma unroll
        for (int ni = 0; ni < 8; ni++)
#pragma unroll
            for (int k = 0; k < 4; k++) acc[mi][ni][k] = 0.f;

    auto issue = [&](int g) {
        if (g < 64) {
            const int d0 = g * 32;
            const uint32_t st = sbase + (g & 3) * STG;
#pragma unroll
            for (int r = 0; r < 6; r++) {
                int idx = tid + r * 256;          // 0..1535
                int c   = idx & 3;
                if (idx < 1024) {
                    int row = idx >> 2;           // 0..255
                    const __nv_bfloat16* src =
                        xb + (size_t)(brow + row) * DDIM + d0 + c * 8;
                    CP16(st + row * ROWB + c * 16, src);
                } else {
                    int row = (idx - 1024) >> 2;  // 0..127
                    const __nv_bfloat16* src =
                        eb + (size_t)(bcode + row) * DDIM + d0 + c * 8;
                    CP16(st + 256 * ROWB + row * ROWB + c * 16, src);
                }
            }
        }
        CP_COMMIT();
    };

    issue(0); issue(1); issue(2);

    const uint32_t aRowOff = (uint32_t)(wm * 64 + (lane & 15)) * ROWB +
                             ((lane >> 4) << 4);
    const uint32_t bRowOff = (uint32_t)(wn * 64 + ((lane >> 4) << 3) + (lane & 7)) * ROWB +
                             (((lane >> 3) & 1) << 4);

    for (int kt = 0; kt < 64; kt++) {
        CP_WAIT2();
        __syncthreads();
        issue(kt + 3);

        const uint32_t aB = sbase + (kt & 3) * STG;
        const uint32_t bB = aB + 256 * ROWB;
#pragma unroll
        for (int kq = 0; kq < 2; kq++) {
            uint32_t aF[4][4];
#pragma unroll
            for (int mi = 0; mi < 4; mi++)
                LDSM_X4(aF[mi], aB + aRowOff + mi * 16 * ROWB + kq * 32);
#pragma unroll
            for (int nj = 0; nj < 4; nj++) {
                uint32_t bF[4];
                LDSM_X4(bF, bB + bRowOff + nj * 16 * ROWB + kq * 32);
#pragma unroll
                for (int mi = 0; mi < 4; mi++) {
                    MMA_BF16(acc[mi][nj * 2 + 0], aF[mi], bF[0], bF[1]);
                    MMA_BF16(acc[mi][nj * 2 + 1], aF[mi], bF[2], bF[3]);
                }
            }
        }
        __syncthreads();
    }

#pragma unroll
    for (int mi = 0; mi < 4; mi++)
#pragma unroll
        for (int half = 0; half < 2; half++) {
            int row = brow + wm * 64 + mi * 16 + (lane >> 2) + half * 8;
#pragma unroll
            for (int ni = 0; ni < 8; ni++) {
                int code = bcode + wn * 64 + ni * 8 + (lane & 3) * 2;
                float2 v = make_float2(acc[mi][ni][half * 2 + 0],
                                       acc[mi][ni][half * 2 + 1]);
                *reinterpret_cast<float2*>(&g_scores[(size_t)row * KCODES + code]) = v;
            }
        }
}

// ---------------------------------------------------------------------------
// Pass 2: per row, bf16-score max; rescore candidates within MARGIN exactly.
// ---------------------------------------------------------------------------
#define MARGIN 4.0f

__global__ __launch_bounds__(256)
void pass2_rescue(const float* __restrict__ x, const float* __restrict__ e) {
    const int lane = threadIdx.x & 31;
    const int row  = blockIdx.x * 8 + (threadIdx.x >> 5);

    float sc[32];
    float rowmax = -3.4e38f;
    const float* srow = &g_scores[(size_t)row * KCODES];
#pragma unroll
    for (int k = 0; k < 32; k++) {
        sc[k] = srow[k * 32 + lane] - g_enorm[k * 32 + lane];
        rowmax = fmaxf(rowmax, sc[k]);
    }
#pragma unroll
    for (int o = 16; o; o >>= 1)
        rowmax = fmaxf(rowmax, __shfl_xor_sync(0xffffffffu, rowmax, o));
    const float thr = rowmax - MARGIN;

    float xr[64];
    const float* xrow = x + (size_t)row * DDIM;
#pragma unroll
    for (int j = 0; j < 64; j++) xr[j] = xrow[j * 32 + lane];

    float bestS = -3.4e38f;
    int   bestI = 0;
#pragma unroll 1
    for (int k = 0; k < 32; k++) {
        unsigned m = __ballot_sync(0xffffffffu, sc[k] >= thr);
        while (m) {
            int l = __ffs(m) - 1;
            m &= m - 1;
            int c = k * 32 + l;
            const float* er = e + (size_t)c * DDIM;
            float p = 0.f;
#pragma unroll
            for (int j = 0; j < 64; j++) p = fmaf(xr[j], er[j * 32 + lane], p);
#pragma unroll
            for (int o = 16; o; o >>= 1) p += __shfl_xor_sync(0xffffffffu, p, o);
            float s = p - g_enorm[c];
            if (s > bestS) { bestS = s; bestI = c; }
        }
    }
    if (lane == 0) g_best[row] = bestI;
}

// ---------------------------------------------------------------------------
__global__ void gather_kernel(const float* __restrict__ e,
                              float* __restrict__ out) {
    int n = blockIdx.x;
    int best = g_best[n];
    const float4* src = reinterpret_cast<const float4*>(e + (size_t)best * DDIM);
    float4* dst = reinterpret_cast<float4*>(out + (size_t)n * DDIM);
#pragma unroll
    for (int r = 0; r < 2; r++)
        dst[threadIdx.x + r * 256] = src[threadIdx.x + r * 256];
}

__global__ void tail_kernel(float* __restrict__ out, int extra) {
    for (int i = blockIdx.x * blockDim.x + threadIdx.x; i < extra;
         i += gridDim.x * blockDim.x) {
        int n = (i < N_ROWS) ? i : (N_ROWS - 1);
        out[(size_t)N_ROWS * DDIM + i] = (float)g_best[n];
    }
}

// ---------------------------------------------------------------------------
extern "C" void kernel_launch(void* const* d_in, const int* in_sizes, int n_in,
                              void* d_out, int out_size) {
    const float* x = (const float*)d_in[0];
    const float* e = (const float*)d_in[1];
    float* out = (float*)d_out;

    static __nv_bfloat16* xb_p = nullptr;
    if (!xb_p) {
        cudaGetSymbolAddress((void**)&xb_p, g_xb);
        cudaFuncSetAttribute(pass1_gemm,
                             cudaFuncAttributeMaxDynamicSharedMemorySize, SMEM_P1);
    }
    __nv_bfloat16* eb_p; cudaGetSymbolAddress((void**)&eb_p, g_eb);

    convert_kernel<<<1024, 256>>>(x, xb_p, N_ROWS * DDIM / 4);
    convert_kernel<<<256, 256>>>(e, eb_p, KCODES * DDIM / 4);
    enorm_kernel<<<KCODES, 256>>>(e);

    dim3 g1(KCODES / 128, N_ROWS / 256);   // (8, 64) = 512 CTAs
    pass1_gemm<<<g1, 256, SMEM_P1>>>();

    pass2_rescue<<<N_ROWS / 8, 256>>>(x, e);
    gather_kernel<<<N_ROWS, 256>>>(e, out);

    int extra = out_size - N_ROWS * DDIM;
    if (extra > 0) {
        int blocks = (extra + 255) / 256;
        if (blocks > 148) blocks = 148;
        tail_kernel<<<blocks, 256>>>(out, extra);
    }
}

// round 6
// speedup vs baseline: 1.2193x; 1.2193x over previous
#include <cuda_runtime.h>
#include <cuda_bf16.h>
#include <cstdint>

#define N_ROWS 16384
#define DDIM   2048
#define KCODES 1024
#define MARGIN 4.0f

__device__ float g_enorm[KCODES];
__device__ float g_cmax[(size_t)N_ROWS * 8];            // per (row, chunk) bf16-score max
__device__ ulonglong2 g_cmask[(size_t)N_ROWS * 8];      // per (row, chunk) candidate bits
__device__ __nv_bfloat16 g_xb[(size_t)N_ROWS * DDIM];
__device__ __nv_bfloat16 g_eb[(size_t)KCODES * DDIM];

// ---------------------------------------------------------------------------
#define ROWB   80                   // 64B payload + 16B pad (ldmatrix conflict-free)
#define STG    (256 * ROWB)         // stage: A 128 rows + B 128 rows = 20480 B
#define EPN    (4 * STG)            // enorm chunk  (512 B)
#define EPMAX  (EPN + 512)          // float rowmax[128][2] (1024 B)
#define EPMSK  (EPMAX + 1024)       // u64 rowmask[128][2]  (2048 B)
#define SMEM_P1 (EPMSK + 2048)      // 85504

static __device__ __forceinline__ uint32_t smem_u32(const void* p) {
    uint32_t a;
    asm("{ .reg .u64 t; cvta.to.shared.u64 t, %1; cvt.u32.u64 %0, t; }"
        : "=r"(a) : "l"(p));
    return a;
}

#define LDSM_X4(r, addr)                                                     \
    asm volatile("ldmatrix.sync.aligned.m8n8.x4.shared.b16 {%0,%1,%2,%3}, [%4];" \
        : "=r"((r)[0]), "=r"((r)[1]), "=r"((r)[2]), "=r"((r)[3]) : "r"(addr))

#define MMA_BF16(d, a, b0, b1)                                               \
    asm volatile("mma.sync.aligned.m16n8k16.row.col.f32.bf16.bf16.f32 "      \
        "{%0,%1,%2,%3}, {%4,%5,%6,%7}, {%8,%9}, {%0,%1,%2,%3};"              \
        : "+f"((d)[0]), "+f"((d)[1]), "+f"((d)[2]), "+f"((d)[3])             \
        : "r"((a)[0]), "r"((a)[1]), "r"((a)[2]), "r"((a)[3]),                \
          "r"(b0), "r"(b1))

#define CP16(dst, src)                                                       \
    asm volatile("cp.async.ca.shared.global [%0], [%1], 16;"                 \
                 :: "r"(dst), "l"(src))
#define CP_COMMIT() asm volatile("cp.async.commit_group;" ::: "memory")
#define CP_WAIT2()  asm volatile("cp.async.wait_group 2;" ::: "memory")

// ---------------------------------------------------------------------------
__global__ void convert_kernel(const float* __restrict__ src,
                               __nv_bfloat16* __restrict__ dst, int n4) {
    for (int i = blockIdx.x * blockDim.x + threadIdx.x; i < n4;
         i += gridDim.x * blockDim.x) {
        float4 v = reinterpret_cast<const float4*>(src)[i];
        __nv_bfloat162 a = __floats2bfloat162_rn(v.x, v.y);
        __nv_bfloat162 b = __floats2bfloat162_rn(v.z, v.w);
        uint2 u; memcpy(&u.x, &a, 4); memcpy(&u.y, &b, 4);
        reinterpret_cast<uint2*>(dst)[i] = u;
    }
}

// convert e to bf16 AND compute 0.5*||e||^2 in one pass
__global__ void conv_enorm_kernel(const float* __restrict__ e,
                                  __nv_bfloat16* __restrict__ eb) {
    int k = blockIdx.x;
    const float4* row = reinterpret_cast<const float4*>(e + (size_t)k * DDIM);
    uint2* drow = reinterpret_cast<uint2*>(eb + (size_t)k * DDIM);
    float s = 0.f;
#pragma unroll
    for (int r = 0; r < 2; r++) {
        int i = threadIdx.x + r * 256;
        float4 v = row[i];
        s += v.x * v.x + v.y * v.y + v.z * v.z + v.w * v.w;
        __nv_bfloat162 a = __floats2bfloat162_rn(v.x, v.y);
        __nv_bfloat162 b = __floats2bfloat162_rn(v.z, v.w);
        uint2 u; memcpy(&u.x, &a, 4); memcpy(&u.y, &b, 4);
        drow[i] = u;
    }
#pragma unroll
    for (int o = 16; o; o >>= 1) s += __shfl_xor_sync(0xffffffffu, s, o);
    __shared__ float ss[8];
    if ((threadIdx.x & 31) == 0) ss[threadIdx.x >> 5] = s;
    __syncthreads();
    if (threadIdx.x == 0) {
        float t = 0.f;
        for (int i = 0; i < 8; i++) t += ss[i];
        g_enorm[k] = 0.5f * t;
    }
}

// ---------------------------------------------------------------------------
// Pass 1: bf16 HMMA GEMM (128x128 CTA tile, 32x64 warp tile, 4-stage
// cp.async). Epilogue reduces to per-(row,chunk) {max, candidate mask}.
// ---------------------------------------------------------------------------
__global__ __launch_bounds__(256, 2)
void pass1_gemm(void) {
    extern __shared__ char smem[];
    const uint32_t sbase = smem_u32(smem);

    const int tid  = threadIdx.x;
    const int lane = tid & 31;
    const int wid  = tid >> 5;
    const int wm   = wid & 3;
    const int wn   = wid >> 2;
    const int brow  = blockIdx.y * 128;
    const int bcode = blockIdx.x * 128;
    const int cidx  = blockIdx.x;

    float* ep_en = reinterpret_cast<float*>(smem + EPN);
    float* rmax  = reinterpret_cast<float*>(smem + EPMAX);              // [128][2]
    unsigned long long* rmask =
        reinterpret_cast<unsigned long long*>(smem + EPMSK);           // [128][2]

    if (tid < 128) ep_en[tid] = g_enorm[bcode + tid];

    const __nv_bfloat16* xb = g_xb;
    const __nv_bfloat16* eb = g_eb;

    float acc[2][8][4];
#pragma unroll
    for (int mi = 0; mi < 2; mi++)
#pragma unroll
        for (int ni = 0; ni < 8; ni++)
#pragma unroll
            for (int k = 0; k < 4; k++) acc[mi][ni][k] = 0.f;

    auto issue = [&](int g) {
        if (g < 64) {
            const int d0 = g * 32;
            const uint32_t st = sbase + (g & 3) * STG;
#pragma unroll
            for (int r = 0; r < 4; r++) {
                int idx = tid + r * 256;
                int c   = idx & 3;
                if (idx < 512) {
                    int row = idx >> 2;
                    CP16(st + row * ROWB + c * 16,
                         xb + (size_t)(brow + row) * DDIM + d0 + c * 8);
                } else {
                    int row = (idx - 512) >> 2;
                    CP16(st + 128 * ROWB + row * ROWB + c * 16,
                         eb + (size_t)(bcode + row) * DDIM + d0 + c * 8);
                }
            }
        }
        CP_COMMIT();
    };

    issue(0); issue(1); issue(2);

    const uint32_t aRowOff = (uint32_t)(wm * 32 + (lane & 15)) * ROWB +
                             ((lane >> 4) << 4);
    const uint32_t bRowOff = (uint32_t)(wn * 64 + ((lane >> 4) << 3) + (lane & 7)) * ROWB +
                             (((lane >> 3) & 1) << 4);

    for (int kt = 0; kt < 64; kt++) {
        CP_WAIT2();
        __syncthreads();
        issue(kt + 3);

        const uint32_t aB = sbase + (kt & 3) * STG;
        const uint32_t bB = aB + 128 * ROWB;
#pragma unroll
        for (int kq = 0; kq < 2; kq++) {
            uint32_t aF[2][4];
#pragma unroll
            for (int mi = 0; mi < 2; mi++)
                LDSM_X4(aF[mi], aB + aRowOff + mi * 16 * ROWB + kq * 32);
#pragma unroll
            for (int nj = 0; nj < 4; nj++) {
                uint32_t bF[4];
                LDSM_X4(bF, bB + bRowOff + nj * 16 * ROWB + kq * 32);
#pragma unroll
                for (int mi = 0; mi < 2; mi++) {
                    MMA_BF16(acc[mi][nj * 2 + 0], aF[mi], bF[0], bF[1]);
                    MMA_BF16(acc[mi][nj * 2 + 1], aF[mi], bF[2], bF[3]);
                }
            }
        }
    }
    __syncthreads();

    // ---- epilogue: per-row chunk max ----
#pragma unroll
    for (int mi = 0; mi < 2; mi++)
#pragma unroll
        for (int half = 0; half < 2; half++) {
            int row = wm * 32 + mi * 16 + (lane >> 2) + half * 8;
            float m = -3.4e38f;
#pragma unroll
            for (int ni = 0; ni < 8; ni++)
#pragma unroll
                for (int e2 = 0; e2 < 2; e2++) {
                    int cl = wn * 64 + ni * 8 + (lane & 3) * 2 + e2;
                    m = fmaxf(m, acc[mi][ni][half * 2 + e2] - ep_en[cl]);
                }
            m = fmaxf(m, __shfl_xor_sync(0xffffffffu, m, 1));
            m = fmaxf(m, __shfl_xor_sync(0xffffffffu, m, 2));
            if ((lane & 3) == 0) rmax[row * 2 + wn] = m;
        }
    __syncthreads();

    // ---- epilogue: candidate masks ----
#pragma unroll
    for (int mi = 0; mi < 2; mi++)
#pragma unroll
        for (int half = 0; half < 2; half++) {
            int row = wm * 32 + mi * 16 + (lane >> 2) + half * 8;
            float th = fmaxf(rmax[row * 2], rmax[row * 2 + 1]) - MARGIN;
            unsigned long long mb = 0ull;
#pragma unroll
            for (int ni = 0; ni < 8; ni++)
#pragma unroll
                for (int e2 = 0; e2 < 2; e2++) {
                    int p = ni * 8 + (lane & 3) * 2 + e2;
                    float s = acc[mi][ni][half * 2 + e2] - ep_en[wn * 64 + p];
                    if (s >= th) mb |= (1ull << p);
                }
            mb |= __shfl_xor_sync(0xffffffffu, mb, 1);
            mb |= __shfl_xor_sync(0xffffffffu, mb, 2);
            if ((lane & 3) == 0) rmask[row * 2 + wn] = mb;
        }
    __syncthreads();

    if (tid < 128) {
        int grow = brow + tid;
        g_cmax[(size_t)grow * 8 + cidx] = fmaxf(rmax[tid * 2], rmax[tid * 2 + 1]);
        g_cmask[(size_t)grow * 8 + cidx] =
            make_ulonglong2(rmask[tid * 2], rmask[tid * 2 + 1]);
    }
}

// ---------------------------------------------------------------------------
// Pass 2 (fused rescue + gather + index tail): one warp per row.
// ---------------------------------------------------------------------------
__global__ __launch_bounds__(256)
void pass2_gather(const float* __restrict__ x, const float* __restrict__ e,
                  float* __restrict__ out, int extra) {
    const int lane = threadIdx.x & 31;
    const int row  = blockIdx.x * 8 + (threadIdx.x >> 5);

    float gmax = -3.4e38f;
#pragma unroll
    for (int j = 0; j < 8; j++)
        gmax = fmaxf(gmax, g_cmax[(size_t)row * 8 + j]);
    const float thr = gmax - MARGIN;

    float xr[64];
    const float* xrow = x + (size_t)row * DDIM;
#pragma unroll
    for (int j = 0; j < 64; j++) xr[j] = xrow[j * 32 + lane];

    float bestS = -3.4e38f;
    int   bestI = 0;
#pragma unroll 1
    for (int c8 = 0; c8 < 8; c8++) {
        if (g_cmax[(size_t)row * 8 + c8] < thr) continue;
        ulonglong2 mk = g_cmask[(size_t)row * 8 + c8];
#pragma unroll 1
        for (int half = 0; half < 2; half++) {
            unsigned long long m = half ? mk.y : mk.x;
            while (m) {
                int b = __ffsll((long long)m) - 1;
                m &= m - 1;
                int c = c8 * 128 + half * 64 + b;
                const float* er = e + (size_t)c * DDIM;
                float p = 0.f;
#pragma unroll
                for (int j = 0; j < 64; j++)
                    p = fmaf(xr[j], er[j * 32 + lane], p);
#pragma unroll
                for (int o = 16; o; o >>= 1)
                    p += __shfl_xor_sync(0xffffffffu, p, o);
                float s = p - g_enorm[c];
                if (s > bestS) { bestS = s; bestI = c; }  // ascending c: first-hit ties
            }
        }
    }

    // gather codebook row into output
    const float4* src = reinterpret_cast<const float4*>(e + (size_t)bestI * DDIM);
    float4* dst = reinterpret_cast<float4*>(out + (size_t)row * DDIM);
#pragma unroll
    for (int r = 0; r < 16; r++) dst[lane + r * 32] = src[lane + r * 32];

    if (lane == 0 && row < extra)
        out[(size_t)N_ROWS * DDIM + row] = (float)bestI;
}

// spill tail (only if out has more than N_ROWS extra elements; clamp like R1)
__global__ void tail_spill(float* __restrict__ out, int extra) {
    float v = out[(size_t)N_ROWS * DDIM + (N_ROWS - 1)];
    for (int i = N_ROWS + blockIdx.x * blockDim.x + threadIdx.x; i < extra;
         i += gridDim.x * blockDim.x)
        out[(size_t)N_ROWS * DDIM + i] = v;
}

// ---------------------------------------------------------------------------
extern "C" void kernel_launch(void* const* d_in, const int* in_sizes, int n_in,
                              void* d_out, int out_size) {
    const float* x = (const float*)d_in[0];
    const float* e = (const float*)d_in[1];
    float* out = (float*)d_out;

    static __nv_bfloat16* xb_p = nullptr;
    static __nv_bfloat16* eb_p = nullptr;
    if (!xb_p) {
        cudaGetSymbolAddress((void**)&xb_p, g_xb);
        cudaGetSymbolAddress((void**)&eb_p, g_eb);
        cudaFuncSetAttribute(pass1_gemm,
                             cudaFuncAttributeMaxDynamicSharedMemorySize, SMEM_P1);
    }

    int extra = out_size - N_ROWS * DDIM;

    convert_kernel<<<1024, 256>>>(x, xb_p, N_ROWS * DDIM / 4);
    conv_enorm_kernel<<<KCODES, 256>>>(e, eb_p);

    dim3 g1(KCODES / 128, N_ROWS / 128);   // (8, 128)
    pass1_gemm<<<g1, 256, SMEM_P1>>>();

    pass2_gather<<<N_ROWS / 8, 256>>>(x, e, out, extra);

    if (extra > N_ROWS)
        tail_spill<<<64, 256>>>(out, extra);
}

// round 7
// speedup vs baseline: 1.2573x; 1.0312x over previous
#include <cuda_runtime.h>
#include <cuda_bf16.h>
#include <cstdint>

#define N_ROWS 16384
#define DDIM   2048
#define KCODES 1024
#define MARGIN 4.0f

__device__ float g_enorm[KCODES];
__device__ float g_cmax[(size_t)N_ROWS * 8];
__device__ ulonglong2 g_cmask[(size_t)N_ROWS * 8];
__device__ __nv_bfloat16 g_xb[(size_t)N_ROWS * DDIM];
__device__ __nv_bfloat16 g_eb[(size_t)KCODES * DDIM];

// ---------------------------------------------------------------------------
#define ROWB   144                 // 128B payload + 16B pad (ldmatrix conflict-free)
#define STG    (256 * ROWB)        // stage: A 128 rows + B 128 rows = 36864 B
#define SMEM_P1 (3 * STG)          // 110592

static __device__ __forceinline__ uint32_t smem_u32(const void* p) {
    uint32_t a;
    asm("{ .reg .u64 t; cvta.to.shared.u64 t, %1; cvt.u32.u64 %0, t; }"
        : "=r"(a) : "l"(p));
    return a;
}

#define LDSM_X4(r, addr)                                                     \
    asm volatile("ldmatrix.sync.aligned.m8n8.x4.shared.b16 {%0,%1,%2,%3}, [%4];" \
        : "=r"((r)[0]), "=r"((r)[1]), "=r"((r)[2]), "=r"((r)[3]) : "r"(addr))

#define MMA_BF16(d, a, b0, b1)                                               \
    asm volatile("mma.sync.aligned.m16n8k16.row.col.f32.bf16.bf16.f32 "      \
        "{%0,%1,%2,%3}, {%4,%5,%6,%7}, {%8,%9}, {%0,%1,%2,%3};"              \
        : "+f"((d)[0]), "+f"((d)[1]), "+f"((d)[2]), "+f"((d)[3])             \
        : "r"((a)[0]), "r"((a)[1]), "r"((a)[2]), "r"((a)[3]),                \
          "r"(b0), "r"(b1))

#define CP16(dst, src)                                                       \
    asm volatile("cp.async.ca.shared.global [%0], [%1], 16;"                 \
                 :: "r"(dst), "l"(src))
#define CP_COMMIT() asm volatile("cp.async.commit_group;" ::: "memory")
#define CP_WAIT1()  asm volatile("cp.async.wait_group 1;" ::: "memory")
#define CP_WAIT0()  asm volatile("cp.async.wait_group 0;" ::: "memory")

// ---------------------------------------------------------------------------
__global__ void convert_kernel(const float* __restrict__ src,
                               __nv_bfloat16* __restrict__ dst, int n4) {
    for (int i = blockIdx.x * blockDim.x + threadIdx.x; i < n4;
         i += gridDim.x * blockDim.x) {
        float4 v = reinterpret_cast<const float4*>(src)[i];
        __nv_bfloat162 a = __floats2bfloat162_rn(v.x, v.y);
        __nv_bfloat162 b = __floats2bfloat162_rn(v.z, v.w);
        uint2 u; memcpy(&u.x, &a, 4); memcpy(&u.y, &b, 4);
        reinterpret_cast<uint2*>(dst)[i] = u;
    }
}

__global__ void conv_enorm_kernel(const float* __restrict__ e,
                                  __nv_bfloat16* __restrict__ eb) {
    int k = blockIdx.x;
    const float4* row = reinterpret_cast<const float4*>(e + (size_t)k * DDIM);
    uint2* drow = reinterpret_cast<uint2*>(eb + (size_t)k * DDIM);
    float s = 0.f;
#pragma unroll
    for (int r = 0; r < 2; r++) {
        int i = threadIdx.x + r * 256;
        float4 v = row[i];
        s += v.x * v.x + v.y * v.y + v.z * v.z + v.w * v.w;
        __nv_bfloat162 a = __floats2bfloat162_rn(v.x, v.y);
        __nv_bfloat162 b = __floats2bfloat162_rn(v.z, v.w);
        uint2 u; memcpy(&u.x, &a, 4); memcpy(&u.y, &b, 4);
        drow[i] = u;
    }
#pragma unroll
    for (int o = 16; o; o >>= 1) s += __shfl_xor_sync(0xffffffffu, s, o);
    __shared__ float ss[8];
    if ((threadIdx.x & 31) == 0) ss[threadIdx.x >> 5] = s;
    __syncthreads();
    if (threadIdx.x == 0) {
        float t = 0.f;
        for (int i = 0; i < 8; i++) t += ss[i];
        g_enorm[k] = 0.5f * t;
    }
}

// ---------------------------------------------------------------------------
// Pass 1: bf16 HMMA GEMM (128x128 CTA, 32x64 warp, KT=64, 3-stage cp.async).
// Epilogue (overlaying stage smem) -> per-(row,chunk) {max, candidate mask}.
// ---------------------------------------------------------------------------
__global__ __launch_bounds__(256, 2)
void pass1_gemm(void) {
    extern __shared__ char smem[];
    const uint32_t sbase = smem_u32(smem);

    const int tid  = threadIdx.x;
    const int lane = tid & 31;
    const int wid  = tid >> 5;
    const int wm   = wid & 3;
    const int wn   = wid >> 2;
    const int brow  = blockIdx.y * 128;
    const int bcode = blockIdx.x * 128;
    const int cidx  = blockIdx.x;

    const __nv_bfloat16* xb = g_xb;
    const __nv_bfloat16* eb = g_eb;

    float acc[2][8][4];
#pragma unroll
    for (int mi = 0; mi < 2; mi++)
#pragma unroll
        for (int ni = 0; ni < 8; ni++)
#pragma unroll
            for (int k = 0; k < 4; k++) acc[mi][ni][k] = 0.f;

    auto issue = [&](int g) {
        if (g < 32) {
            const int d0 = g * 64;
            const uint32_t st = sbase + (g % 3) * STG;
#pragma unroll
            for (int r = 0; r < 8; r++) {
                int idx = tid + r * 256;          // 0..2047
                int c   = idx & 7;
                int row = idx >> 3;               // 0..255
                const __nv_bfloat16* src = (row < 128)
                    ? xb + (size_t)(brow + row) * DDIM + d0 + c * 8
                    : eb + (size_t)(bcode + row - 128) * DDIM + d0 + c * 8;
                CP16(st + row * ROWB + c * 16, src);
            }
        }
        CP_COMMIT();
    };

    issue(0); issue(1);

    const uint32_t aRowOff = (uint32_t)(wm * 32 + (lane & 15)) * ROWB +
                             ((lane >> 4) << 4);
    const uint32_t bRowOff = (uint32_t)(128 + wn * 64 + ((lane >> 4) << 3) + (lane & 7)) * ROWB +
                             (((lane >> 3) & 1) << 4);

    for (int kt = 0; kt < 32; kt++) {
        CP_WAIT1();
        __syncthreads();
        issue(kt + 2);

        const uint32_t aB = sbase + (kt % 3) * STG;
#pragma unroll
        for (int kq = 0; kq < 4; kq++) {
            uint32_t aF[2][4];
#pragma unroll
            for (int mi = 0; mi < 2; mi++)
                LDSM_X4(aF[mi], aB + aRowOff + mi * 16 * ROWB + kq * 32);
#pragma unroll
            for (int nj = 0; nj < 4; nj++) {
                uint32_t bF[4];
                LDSM_X4(bF, aB + bRowOff + nj * 16 * ROWB + kq * 32);
#pragma unroll
                for (int mi = 0; mi < 2; mi++) {
                    MMA_BF16(acc[mi][nj * 2 + 0], aF[mi], bF[0], bF[1]);
                    MMA_BF16(acc[mi][nj * 2 + 1], aF[mi], bF[2], bF[3]);
                }
            }
        }
    }
    CP_WAIT0();
    __syncthreads();

    // ---- epilogue (overlays stage smem) ----
    float* ep_en = reinterpret_cast<float*>(smem);                    // 512 B
    float* rmax  = reinterpret_cast<float*>(smem + 512);              // [128][2]
    unsigned long long* rmask =
        reinterpret_cast<unsigned long long*>(smem + 1536);           // [128][2]

    if (tid < 128) ep_en[tid] = g_enorm[bcode + tid];
    __syncthreads();

#pragma unroll
    for (int mi = 0; mi < 2; mi++)
#pragma unroll
        for (int half = 0; half < 2; half++) {
            int row = wm * 32 + mi * 16 + (lane >> 2) + half * 8;
            float m = -3.4e38f;
#pragma unroll
            for (int ni = 0; ni < 8; ni++)
#pragma unroll
                for (int e2 = 0; e2 < 2; e2++) {
                    int cl = wn * 64 + ni * 8 + (lane & 3) * 2 + e2;
                    m = fmaxf(m, acc[mi][ni][half * 2 + e2] - ep_en[cl]);
                }
            m = fmaxf(m, __shfl_xor_sync(0xffffffffu, m, 1));
            m = fmaxf(m, __shfl_xor_sync(0xffffffffu, m, 2));
            if ((lane & 3) == 0) rmax[row * 2 + wn] = m;
        }
    __syncthreads();

#pragma unroll
    for (int mi = 0; mi < 2; mi++)
#pragma unroll
        for (int half = 0; half < 2; half++) {
            int row = wm * 32 + mi * 16 + (lane >> 2) + half * 8;
            float th = fmaxf(rmax[row * 2], rmax[row * 2 + 1]) - MARGIN;
            unsigned long long mb = 0ull;
#pragma unroll
            for (int ni = 0; ni < 8; ni++)
#pragma unroll
                for (int e2 = 0; e2 < 2; e2++) {
                    int p = ni * 8 + (lane & 3) * 2 + e2;
                    float s = acc[mi][ni][half * 2 + e2] - ep_en[wn * 64 + p];
                    if (s >= th) mb |= (1ull << p);
                }
            mb |= __shfl_xor_sync(0xffffffffu, mb, 1);
            mb |= __shfl_xor_sync(0xffffffffu, mb, 2);
            if ((lane & 3) == 0) rmask[row * 2 + wn] = mb;
        }
    __syncthreads();

    if (tid < 128) {
        int grow = brow + tid;
        g_cmax[(size_t)grow * 8 + cidx] = fmaxf(rmax[tid * 2], rmax[tid * 2 + 1]);
        g_cmask[(size_t)grow * 8 + cidx] =
            make_ulonglong2(rmask[tid * 2], rmask[tid * 2 + 1]);
    }
}

// ---------------------------------------------------------------------------
// Pass 2 (fused rescue + gather): one warp per row. Lazy exact rescore —
// single-candidate rows never touch x.
// ---------------------------------------------------------------------------
__global__ __launch_bounds__(256)
void pass2_gather(const float* __restrict__ x, const float* __restrict__ e,
                  float* __restrict__ out, int extra) {
    const int lane = threadIdx.x & 31;
    const int row  = blockIdx.x * 8 + (threadIdx.x >> 5);

    float cm[8];
    float gmax = -3.4e38f;
#pragma unroll
    for (int j = 0; j < 8; j++) {
        cm[j] = g_cmax[(size_t)row * 8 + j];
        gmax = fmaxf(gmax, cm[j]);
    }
    const float thr = gmax - MARGIN;

    // collect candidates (ascending code order)
    int ncand = 0;
    int firstI = 0;
    ulonglong2 mk[8];
#pragma unroll
    for (int c8 = 0; c8 < 8; c8++) {
        mk[c8] = make_ulonglong2(0ull, 0ull);
        if (cm[c8] < thr) continue;
        mk[c8] = g_cmask[(size_t)row * 8 + c8];
        int p0 = __popcll(mk[c8].x), p1 = __popcll(mk[c8].y);
        if (ncand == 0) {
            if (p0) firstI = c8 * 128 + __ffsll((long long)mk[c8].x) - 1;
            else if (p1) firstI = c8 * 128 + 64 + __ffsll((long long)mk[c8].y) - 1;
        }
        ncand += p0 + p1;
    }

    int bestI = firstI;
    if (ncand > 1) {
        const float* xrow = x + (size_t)row * DDIM;
        float bestS = -3.4e38f;
#pragma unroll 1
        for (int c8 = 0; c8 < 8; c8++) {
#pragma unroll 1
            for (int half = 0; half < 2; half++) {
                unsigned long long m = half ? mk[c8].y : mk[c8].x;
                while (m) {
                    int b = __ffsll((long long)m) - 1;
                    m &= m - 1;
                    int c = c8 * 128 + half * 64 + b;
                    const float* er = e + (size_t)c * DDIM;
                    float p = 0.f;
#pragma unroll
                    for (int j = 0; j < 64; j++)
                        p = fmaf(xrow[j * 32 + lane], er[j * 32 + lane], p);
#pragma unroll
                    for (int o = 16; o; o >>= 1)
                        p += __shfl_xor_sync(0xffffffffu, p, o);
                    float s = p - g_enorm[c];
                    if (s > bestS) { bestS = s; bestI = c; }
                }
            }
        }
    }

    // gather codebook row into output
    const float4* src = reinterpret_cast<const float4*>(e + (size_t)bestI * DDIM);
    float4* dst = reinterpret_cast<float4*>(out + (size_t)row * DDIM);
#pragma unroll
    for (int r = 0; r < 16; r++) dst[lane + r * 32] = src[lane + r * 32];

    if (lane == 0 && row < extra)
        out[(size_t)N_ROWS * DDIM + row] = (float)bestI;
}

__global__ void tail_spill(float* __restrict__ out, int extra) {
    float v = out[(size_t)N_ROWS * DDIM + (N_ROWS - 1)];
    for (int i = N_ROWS + blockIdx.x * blockDim.x + threadIdx.x; i < extra;
         i += gridDim.x * blockDim.x)
        out[(size_t)N_ROWS * DDIM + i] = v;
}

// ---------------------------------------------------------------------------
extern "C" void kernel_launch(void* const* d_in, const int* in_sizes, int n_in,
                              void* d_out, int out_size) {
    const float* x = (const float*)d_in[0];
    const float* e = (const float*)d_in[1];
    float* out = (float*)d_out;

    static __nv_bfloat16* xb_p = nullptr;
    static __nv_bfloat16* eb_p = nullptr;
    if (!xb_p) {
        cudaGetSymbolAddress((void**)&xb_p, g_xb);
        cudaGetSymbolAddress((void**)&eb_p, g_eb);
        cudaFuncSetAttribute(pass1_gemm,
                             cudaFuncAttributeMaxDynamicSharedMemorySize, SMEM_P1);
    }

    int extra = out_size - N_ROWS * DDIM;

    convert_kernel<<<1024, 256>>>(x, xb_p, N_ROWS * DDIM / 4);
    conv_enorm_kernel<<<KCODES, 256>>>(e, eb_p);

    dim3 g1(KCODES / 128, N_ROWS / 128);   // (8, 128)
    pass1_gemm<<<g1, 256, SMEM_P1>>>();

    pass2_gather<<<N_ROWS / 8, 256>>>(x, e, out, extra);

    if (extra > N_ROWS)
        tail_spill<<<64, 256>>>(out, extra);
}